// round 4
// baseline (speedup 1.0000x reference)
#include <cuda_runtime.h>
#include <math.h>

// Problem constants
#define BSZ 16384
#define DD  512
#define KC  1024
#define ALPHA 10.0f
#define BETA  0.25f

// Output layout: concatenated flattened outputs of the reference tuple,
// all as float32:
//  quantized [B,D], vq_loss [1], entropy_vq [1], argm [B], hard_quantized [B,D],
//  soft_assign [B,K], cluster_metric [1]
// NOTE: OFF_HQ and OFF_SA are == 2 (mod 4) floats -> only 8-byte aligned.
// Any access through them must be at most float2-wide.
#define OFF_Q   ((size_t)0)
#define OFF_VQ  ((size_t)(BSZ*DD))
#define OFF_ENT (OFF_VQ + 1)
#define OFF_ARG (OFF_ENT + 1)
#define OFF_HQ  (OFF_ARG + BSZ)
#define OFF_SA  (OFF_HQ + (size_t)BSZ*DD)
#define OFF_CM  (OFF_SA + (size_t)BSZ*KC)

// Scratch (device globals; no allocation allowed)
__device__ float  g_ln[(size_t)BSZ * DD];   // normalized latents   (33.5 MB)
__device__ float  g_cbn[(size_t)KC * DD];   // normalized codebook  ( 2 MB)
__device__ float  g_att[(size_t)BSZ * KC];  // attention logits     (67 MB)
__device__ float  g_avg[KC];                // column sums of soft_assign
__device__ double g_mse_sum;
__device__ double g_max_sum;

// ---------------------------------------------------------------------------
__global__ void init_kernel() {
    int t = threadIdx.x;
    if (t < KC) g_avg[t] = 0.0f;
    if (t == 0) { g_mse_sum = 0.0; g_max_sum = 0.0; }
}

// ---------------------------------------------------------------------------
// Row L2 normalization: y[r,:] = x[r,:] / max(||x[r,:]||, 1e-12)
// One block (128 threads) per row of length 512 (one float4 per thread).
// x and y are 16B-aligned device-global buffers.
__global__ __launch_bounds__(128) void l2norm_kernel(
    const float* __restrict__ x, float* __restrict__ y)
{
    int r = blockIdx.x;
    int t = threadIdx.x;
    const float4* xr = (const float4*)(x + (size_t)r * DD);
    float4 v = xr[t];
    float s = v.x * v.x + v.y * v.y + v.z * v.z + v.w * v.w;
    // warp reduce
    #pragma unroll
    for (int o = 16; o > 0; o >>= 1) s += __shfl_xor_sync(0xffffffffu, s, o);
    __shared__ float sm[4];
    if ((t & 31) == 0) sm[t >> 5] = s;
    __syncthreads();
    float tot = sm[0] + sm[1] + sm[2] + sm[3];
    float inv = 1.0f / fmaxf(sqrtf(tot), 1e-12f);
    float4 o4;
    o4.x = v.x * inv; o4.y = v.y * inv; o4.z = v.z * inv; o4.w = v.w * inv;
    ((float4*)(y + (size_t)r * DD))[t] = o4;
}

// ---------------------------------------------------------------------------
// Tiled SGEMM, 128x128 block tile, 8-deep k tile, 8x8 per thread, 256 threads.
// BT = true : C[M,N] = A[M,Kd] * Bm[N,Kd]^T   (both K-contiguous, A 16B-aligned)
// BT = false: C[M,N] = A[M,Kd] * Bm[Kd,N]     (A only 8B-aligned -> float2 loads)
template <bool BT>
__global__ __launch_bounds__(256) void gemm_kernel(
    const float* __restrict__ A, const float* __restrict__ Bm,
    float* __restrict__ C, int M, int N, int Kd)
{
    __shared__ float As[8][128];
    __shared__ float Bs[8][128];

    int tid = threadIdx.x;
    int bm = blockIdx.y * 128;
    int bn = blockIdx.x * 128;

    int lrow = tid >> 1;          // 0..127
    int lk   = (tid & 1) * 4;     // 0 or 4
    const float* Aptr = A + (size_t)(bm + lrow) * Kd + lk;

    const float* Bptr_t = 0;
    int lkk = 0, lcol = 0;
    if (BT) {
        Bptr_t = Bm + (size_t)(bn + lrow) * Kd + lk;
    } else {
        int lidx = tid * 4;
        lkk  = lidx >> 7;         // 0..7
        lcol = lidx & 127;        // 0..124 step 4
    }

    int tx = tid & 15;
    int ty = tid >> 4;

    float acc[8][8];
    #pragma unroll
    for (int i = 0; i < 8; i++)
        #pragma unroll
        for (int j = 0; j < 8; j++) acc[i][j] = 0.0f;

    for (int k0 = 0; k0 < Kd; k0 += 8) {
        if (BT) {
            // A is 16B-aligned: float4 load
            float4 av = *(const float4*)(Aptr + k0);
            As[lk + 0][lrow] = av.x;
            As[lk + 1][lrow] = av.y;
            As[lk + 2][lrow] = av.z;
            As[lk + 3][lrow] = av.w;
            float4 bv = *(const float4*)(Bptr_t + k0);
            Bs[lk + 0][lrow] = bv.x;
            Bs[lk + 1][lrow] = bv.y;
            Bs[lk + 2][lrow] = bv.z;
            Bs[lk + 3][lrow] = bv.w;
        } else {
            // A may be only 8B-aligned (soft_assign lives inside d_out at an
            // offset == 2 mod 4 floats): two float2 loads
            float2 a0 = *(const float2*)(Aptr + k0);
            float2 a1 = *(const float2*)(Aptr + k0 + 2);
            As[lk + 0][lrow] = a0.x;
            As[lk + 1][lrow] = a0.y;
            As[lk + 2][lrow] = a1.x;
            As[lk + 3][lrow] = a1.y;
            float4 bv = *(const float4*)(Bm + (size_t)(k0 + lkk) * N + bn + lcol);
            *(float4*)&Bs[lkk][lcol] = bv;
        }
        __syncthreads();

        #pragma unroll
        for (int kk = 0; kk < 8; kk++) {
            float a[8], b[8];
            #pragma unroll
            for (int i = 0; i < 8; i++) a[i] = As[kk][ty * 8 + i];
            #pragma unroll
            for (int j = 0; j < 8; j++) b[j] = Bs[kk][tx * 8 + j];
            #pragma unroll
            for (int i = 0; i < 8; i++)
                #pragma unroll
                for (int j = 0; j < 8; j++) acc[i][j] += a[i] * b[j];
        }
        __syncthreads();
    }

    #pragma unroll
    for (int i = 0; i < 8; i++) {
        float* cp = C + (size_t)(bm + ty * 8 + i) * N + bn + tx * 8;
        // C is 16B-aligned in both uses (g_att and q_out at offset 0)
        float4 v0 = make_float4(acc[i][0], acc[i][1], acc[i][2], acc[i][3]);
        float4 v1 = make_float4(acc[i][4], acc[i][5], acc[i][6], acc[i][7]);
        *(float4*)(cp + 0) = v0;
        *(float4*)(cp + 4) = v1;
    }
}

// ---------------------------------------------------------------------------
// Per-row softmax(ALPHA*att) + argmax + row-max accumulation + hard_quantized.
// One block (128 threads) per row; 1024 columns -> 8 strided per thread.
// sa and hardq are only 8B-aligned -> scalar / float2 stores only.
__global__ __launch_bounds__(128) void softmax_kernel(
    const float* __restrict__ att, const float* __restrict__ W,
    float* __restrict__ sa, float* __restrict__ argm_out,
    float* __restrict__ hardq)
{
    int row = blockIdx.x;
    int t = threadIdx.x;
    const float* ar = att + (size_t)row * KC;

    float v[8];
    float m = -3.4e38f;
    int mi = 0;
    #pragma unroll
    for (int j = 0; j < 8; j++) {
        int k = t + j * 128;
        float x = ar[k];
        v[j] = x;
        if (x > m) { m = x; mi = k; }
    }

    __shared__ float sm[128];
    __shared__ int   si[128];
    sm[t] = m; si[t] = mi;
    __syncthreads();
    #pragma unroll
    for (int s = 64; s > 0; s >>= 1) {
        if (t < s) {
            float o = sm[t + s]; int oi = si[t + s];
            if (o > sm[t] || (o == sm[t] && oi < si[t])) { sm[t] = o; si[t] = oi; }
        }
        __syncthreads();
    }
    float rowmax = sm[0];
    int arg = si[0];
    __syncthreads();

    float lsum = 0.0f;
    #pragma unroll
    for (int j = 0; j < 8; j++) {
        v[j] = expf(ALPHA * (v[j] - rowmax));
        lsum += v[j];
    }
    sm[t] = lsum;
    __syncthreads();
    #pragma unroll
    for (int s = 64; s > 0; s >>= 1) {
        if (t < s) sm[t] += sm[t + s];
        __syncthreads();
    }
    float inv = 1.0f / sm[0];

    float* sr = sa + (size_t)row * KC;
    #pragma unroll
    for (int j = 0; j < 8; j++) sr[t + j * 128] = v[j] * inv;  // scalar stores

    if (t == 0) {
        argm_out[row] = (float)arg;
        atomicAdd(&g_max_sum, (double)rowmax);
    }
    // hard_quantized[row,:] = W[arg,:]  (hardq only 8B-aligned -> float2)
    const float2* wr = (const float2*)(W + (size_t)arg * DD);
    float2* hq = (float2*)(hardq + (size_t)row * DD);
    hq[2 * t + 0] = wr[2 * t + 0];
    hq[2 * t + 1] = wr[2 * t + 1];
}

// ---------------------------------------------------------------------------
// Column sums of soft_assign (for avg_probs). grid (KC/256, BSZ/1024).
__global__ __launch_bounds__(256) void colsum_kernel(const float* __restrict__ sa)
{
    int k = blockIdx.x * 256 + threadIdx.x;
    int r0 = blockIdx.y * 1024;
    float s = 0.0f;
    for (int r = 0; r < 1024; r++)
        s += sa[(size_t)(r0 + r) * KC + k];
    atomicAdd(&g_avg[k], s);
}

// ---------------------------------------------------------------------------
// MSE(quantized, ln) numerator accumulation.
__global__ __launch_bounds__(256) void mse_kernel(
    const float* __restrict__ q, const float* __restrict__ ln)
{
    const size_t n = (size_t)BSZ * DD;
    size_t i = (size_t)blockIdx.x * blockDim.x + threadIdx.x;
    size_t stride = (size_t)gridDim.x * blockDim.x;
    float s = 0.0f;
    for (; i < n; i += stride) {
        float d = q[i] - ln[i];
        s += d * d;
    }
    #pragma unroll
    for (int o = 16; o > 0; o >>= 1) s += __shfl_xor_sync(0xffffffffu, s, o);
    __shared__ float sm[8];
    int t = threadIdx.x;
    if ((t & 31) == 0) sm[t >> 5] = s;
    __syncthreads();
    if (t == 0) {
        float tot = 0.0f;
        for (int w = 0; w < 8; w++) tot += sm[w];
        atomicAdd(&g_mse_sum, (double)tot);
    }
}

// ---------------------------------------------------------------------------
// Final scalars: vq_loss, entropy_vq, cluster_metric.
__global__ __launch_bounds__(1024) void finalize_kernel(float* __restrict__ out)
{
    int t = threadIdx.x;
    float p = g_avg[t] * (1.0f / (float)BSZ);
    float term = p * logf(p + 1e-10f);
    __shared__ float sm[1024];
    sm[t] = term;
    __syncthreads();
    #pragma unroll
    for (int s = 512; s > 0; s >>= 1) {
        if (t < s) sm[t] += sm[t + s];
        __syncthreads();
    }
    if (t == 0) {
        double mse = g_mse_sum / (double)((size_t)BSZ * DD);
        out[OFF_VQ]  = (float)((1.0 + (double)BETA) * mse);
        out[OFF_ENT] = -sm[0];
        out[OFF_CM]  = (float)(g_max_sum / (double)BSZ);
    }
}

// ---------------------------------------------------------------------------
extern "C" void kernel_launch(void* const* d_in, const int* in_sizes, int n_in,
                              void* d_out, int out_size)
{
    const float* latents = (const float*)d_in[0];   // [B, D]
    const float* emb     = (const float*)d_in[1];   // [K, D]
    float* out = (float*)d_out;

    float* ln  = 0; cudaGetSymbolAddress((void**)&ln,  g_ln);
    float* cbn = 0; cudaGetSymbolAddress((void**)&cbn, g_cbn);
    float* att = 0; cudaGetSymbolAddress((void**)&att, g_att);

    float* q_out  = out + OFF_Q;
    float* arg_out= out + OFF_ARG;
    float* hq_out = out + OFF_HQ;
    float* sa_out = out + OFF_SA;

    init_kernel<<<1, 1024>>>();
    l2norm_kernel<<<KC, 128>>>(emb, cbn);
    l2norm_kernel<<<BSZ, 128>>>(latents, ln);

    // attention = ln [B,D] * cbn[K,D]^T  -> [B,K]
    {
        dim3 grid(KC / 128, BSZ / 128);
        gemm_kernel<true><<<grid, 256>>>(ln, cbn, att, BSZ, KC, DD);
    }

    softmax_kernel<<<BSZ, 128>>>(att, emb, sa_out, arg_out, hq_out);
    {
        dim3 grid(KC / 256, BSZ / 1024);
        colsum_kernel<<<grid, 256>>>(sa_out);
    }

    // quantized = soft_assign [B,K] * W [K,D] -> [B,D]
    {
        dim3 grid(DD / 128, BSZ / 128);
        gemm_kernel<false><<<grid, 256>>>(sa_out, emb, q_out, BSZ, DD, KC);
    }

    mse_kernel<<<2048, 256>>>(q_out, ln);
    finalize_kernel<<<1, 1024>>>(out);
}

// round 7
// speedup vs baseline: 2.0957x; 2.0957x over previous
#include <cuda_runtime.h>
#include <cuda_bf16.h>
#include <math.h>
#include <stdint.h>

// Problem constants
#define BSZ 16384
#define DD  512
#define KC  1024
#define ALPHA 10.0f
#define BETA  0.25f

// Output layout (concatenated fp32):
//  quantized [B,D], vq_loss [1], entropy_vq [1], argm [B], hard_quantized [B,D],
//  soft_assign [B,K], cluster_metric [1]
// OFF_HQ / OFF_SA are == 2 mod 4 floats -> only 8-byte aligned.
#define OFF_Q   ((size_t)0)
#define OFF_VQ  ((size_t)(BSZ*DD))
#define OFF_ENT (OFF_VQ + 1)
#define OFF_ARG (OFF_ENT + 1)
#define OFF_HQ  (OFF_ARG + BSZ)
#define OFF_SA  (OFF_HQ + (size_t)BSZ*DD)
#define OFF_CM  (OFF_SA + (size_t)BSZ*KC)

// ---------------------------------------------------------------------------
// Scratch (device globals; no allocation allowed). bf16 arrays aligned for
// 16-byte cp.async source addresses.
__device__ float  g_ln [(size_t)BSZ * DD];   // normalized latents fp32 (for MSE)
__device__ float  g_att[(size_t)BSZ * KC];   // attention logits
__device__ __align__(128) __nv_bfloat16 g_lnh[(size_t)BSZ * DD];
__device__ __align__(128) __nv_bfloat16 g_lnl[(size_t)BSZ * DD];
__device__ __align__(128) __nv_bfloat16 g_cbh[(size_t)KC * DD];
__device__ __align__(128) __nv_bfloat16 g_cbl[(size_t)KC * DD];
__device__ __align__(128) __nv_bfloat16 g_sah[(size_t)BSZ * KC];
__device__ __align__(128) __nv_bfloat16 g_sal[(size_t)BSZ * KC];
__device__ __align__(128) __nv_bfloat16 g_wth[(size_t)DD * KC];   // W^T hi [D,K]
__device__ __align__(128) __nv_bfloat16 g_wtl[(size_t)DD * KC];   // W^T lo
__device__ float  g_rowmax[BSZ];
__device__ float  g_avg[KC];
__device__ double g_mse_sum;
__device__ double g_max_sum;

// ---------------------------------------------------------------------------
// Baseline-PTX helpers (valid on compute_103): cp.async, ldmatrix, mma.sync
__device__ __forceinline__ uint32_t smem_u32(const void* p) {
    return (uint32_t)__cvta_generic_to_shared(p);
}
__device__ __forceinline__ void cp_async16(uint32_t saddr, const void* gaddr) {
    asm volatile("cp.async.cg.shared.global [%0], [%1], 16;"
                 :: "r"(saddr), "l"(gaddr) : "memory");
}
__device__ __forceinline__ void cp_commit() {
    asm volatile("cp.async.commit_group;" ::: "memory");
}
__device__ __forceinline__ void cp_wait0() {
    asm volatile("cp.async.wait_group 0;" ::: "memory");
}
__device__ __forceinline__ void cp_wait1() {
    asm volatile("cp.async.wait_group 1;" ::: "memory");
}
__device__ __forceinline__ void ldsm_x4(uint32_t& r0, uint32_t& r1,
                                        uint32_t& r2, uint32_t& r3, uint32_t a) {
    asm volatile("ldmatrix.sync.aligned.m8n8.x4.shared.b16 {%0,%1,%2,%3}, [%4];"
                 : "=r"(r0), "=r"(r1), "=r"(r2), "=r"(r3) : "r"(a));
}
__device__ __forceinline__ void mma_bf16(float* c, const uint32_t* a, const uint32_t* b) {
    asm volatile(
        "mma.sync.aligned.m16n8k16.row.col.f32.bf16.bf16.f32 "
        "{%0,%1,%2,%3}, {%4,%5,%6,%7}, {%8,%9}, {%0,%1,%2,%3};"
        : "+f"(c[0]), "+f"(c[1]), "+f"(c[2]), "+f"(c[3])
        : "r"(a[0]), "r"(a[1]), "r"(a[2]), "r"(a[3]), "r"(b[0]), "r"(b[1]));
}

// ---------------------------------------------------------------------------
__global__ void init_kernel() {
    int t = threadIdx.x;
    if (t < KC) g_avg[t] = 0.0f;
    if (t == 0) { g_mse_sum = 0.0; g_max_sum = 0.0; }
}

// ---------------------------------------------------------------------------
// Row L2 normalize + bf16 hi/lo split. One block (128 thr) per row of 512.
template <bool WF32>
__global__ __launch_bounds__(128) void l2norm_split_kernel(
    const float* __restrict__ x, float* __restrict__ y,
    __nv_bfloat16* __restrict__ yh, __nv_bfloat16* __restrict__ yl)
{
    int r = blockIdx.x;
    int t = threadIdx.x;
    const float4* xr = (const float4*)(x + (size_t)r * DD);
    float4 v = xr[t];
    float s = v.x * v.x + v.y * v.y + v.z * v.z + v.w * v.w;
    #pragma unroll
    for (int o = 16; o > 0; o >>= 1) s += __shfl_xor_sync(0xffffffffu, s, o);
    __shared__ float sm[4];
    if ((t & 31) == 0) sm[t >> 5] = s;
    __syncthreads();
    float tot = sm[0] + sm[1] + sm[2] + sm[3];
    float inv = 1.0f / fmaxf(sqrtf(tot), 1e-12f);
    float o4[4] = { v.x * inv, v.y * inv, v.z * inv, v.w * inv };
    if (WF32) {
        ((float4*)(y + (size_t)r * DD))[t] = make_float4(o4[0], o4[1], o4[2], o4[3]);
    }
    size_t base = (size_t)r * DD + t * 4;
    #pragma unroll
    for (int j = 0; j < 4; j++) {
        __nv_bfloat16 h = __float2bfloat16(o4[j]);
        yh[base + j] = h;
        yl[base + j] = __float2bfloat16(o4[j] - __bfloat162float(h));
    }
}

// ---------------------------------------------------------------------------
// W [KC, DD] -> Wt hi/lo [DD, KC]
__global__ __launch_bounds__(1024) void transpose_split_kernel(
    const float* __restrict__ W,
    __nv_bfloat16* __restrict__ th, __nv_bfloat16* __restrict__ tl)
{
    __shared__ float tile[32][33];
    int k0 = blockIdx.x * 32, d0 = blockIdx.y * 32;
    int tx = threadIdx.x & 31, ty = threadIdx.x >> 5;
    tile[ty][tx] = W[(size_t)(k0 + ty) * DD + d0 + tx];
    __syncthreads();
    float v = tile[tx][ty];
    size_t o = (size_t)(d0 + ty) * KC + k0 + tx;
    __nv_bfloat16 h = __float2bfloat16(v);
    th[o] = h;
    tl[o] = __float2bfloat16(v - __bfloat162float(h));
}

// ---------------------------------------------------------------------------
// HMMA (mma.sync bf16) GEMM with bf16x3 compensation:
//   C[M,N] = Ah*Bh + Ah*Bl + Al*Bh   (fp32 accum)
// A: [M,Kd] K-contig hi/lo.  B: [N,Kd] K-contig hi/lo ("col" operand of mma).
// CTA tile 128x128, BK=32, 8 warps (2 in M x 4 in N), warp tile 64x32.
// Double-buffered cp.async smem; rows padded to 80B for conflict-free ldmatrix.
#define GTHREADS 256
#define ROWB   80          // 64B of data + 16B pad per 32-elem row
#define TILE_B (128 * ROWB)          // 10240
#define STAGE_B (4 * TILE_B)         // 40960 (Ah, Al, Bh, Bl)
#define GSMEM_BYTES (2 * STAGE_B)    // 81920

__global__ __launch_bounds__(GTHREADS, 1) void hmma_gemm_kernel(
    const __nv_bfloat16* __restrict__ Ah, const __nv_bfloat16* __restrict__ Al,
    const __nv_bfloat16* __restrict__ Bh, const __nv_bfloat16* __restrict__ Bl,
    float* __restrict__ C, int Ntot, int Kd)
{
    extern __shared__ char smraw[];
    int tid = threadIdx.x;
    int w = tid >> 5, l = tid & 31;
    int wm = w & 1, wn = w >> 1;
    int bm = blockIdx.y * 128;
    int bn = blockIdx.x * 128;

    const __nv_bfloat16* gtile[4] = {
        Ah + (size_t)bm * Kd, Al + (size_t)bm * Kd,
        Bh + (size_t)bn * Kd, Bl + (size_t)bn * Kd };

    uint32_t sbase = smem_u32(smraw);

    // ---- async loader: one BK=32 chunk (4 tiles of 128x32) into stage st
    auto load_stage = [&](int kc, int st) {
        uint32_t sb = sbase + st * STAGE_B;
        #pragma unroll
        for (int it = 0; it < 8; it++) {
            int g = it * GTHREADS + tid;      // 0..2047
            int tile = g >> 9;                // 512 chunks per tile
            int c = g & 511;
            int row = c >> 2;
            int col = c & 3;
            const char* src = (const char*)(gtile[tile] + (size_t)row * Kd + kc * 32)
                              + col * 16;
            cp_async16(sb + tile * TILE_B + row * ROWB + col * 16, src);
        }
        cp_commit();
    };

    float acc[4][4][4];
    #pragma unroll
    for (int i = 0; i < 4; i++)
        #pragma unroll
        for (int j = 0; j < 4; j++)
            #pragma unroll
            for (int q = 0; q < 4; q++) acc[i][j][q] = 0.0f;

    int nch = Kd >> 5;
    load_stage(0, 0);

    for (int kc = 0; kc < nch; kc++) {
        int st = kc & 1;
        if (kc + 1 < nch) { load_stage(kc + 1, st ^ 1); cp_wait1(); }
        else              { cp_wait0(); }
        __syncthreads();

        uint32_t ahb = sbase + st * STAGE_B + 0 * TILE_B;
        uint32_t alb = sbase + st * STAGE_B + 1 * TILE_B;
        uint32_t bhb = sbase + st * STAGE_B + 2 * TILE_B;
        uint32_t blb = sbase + st * STAGE_B + 3 * TILE_B;

        int ldrow = l & 15;
        int ldcol = (l >> 4) * 16;

        #pragma unroll
        for (int kk = 0; kk < 2; kk++) {
            int kb = kk * 32 + ldcol;
            uint32_t a_h[4][4], a_l[4][4];
            #pragma unroll
            for (int mt = 0; mt < 4; mt++) {
                uint32_t off = (uint32_t)(wm * 64 + mt * 16 + ldrow) * ROWB + kb;
                ldsm_x4(a_h[mt][0], a_h[mt][1], a_h[mt][2], a_h[mt][3], ahb + off);
                ldsm_x4(a_l[mt][0], a_l[mt][1], a_l[mt][2], a_l[mt][3], alb + off);
            }
            uint32_t b_h[4][2], b_l[4][2];
            #pragma unroll
            for (int np = 0; np < 2; np++) {
                uint32_t off = (uint32_t)(wn * 32 + np * 16 + ldrow) * ROWB + kb;
                uint32_t r0, r1, r2, r3;
                ldsm_x4(r0, r1, r2, r3, bhb + off);
                b_h[2 * np][0] = r0; b_h[2 * np][1] = r2;
                b_h[2 * np + 1][0] = r1; b_h[2 * np + 1][1] = r3;
                ldsm_x4(r0, r1, r2, r3, blb + off);
                b_l[2 * np][0] = r0; b_l[2 * np][1] = r2;
                b_l[2 * np + 1][0] = r1; b_l[2 * np + 1][1] = r3;
            }
            #pragma unroll
            for (int mt = 0; mt < 4; mt++)
                #pragma unroll
                for (int nt = 0; nt < 4; nt++) {
                    mma_bf16(acc[mt][nt], a_h[mt], b_h[nt]);
                    mma_bf16(acc[mt][nt], a_h[mt], b_l[nt]);
                    mma_bf16(acc[mt][nt], a_l[mt], b_h[nt]);
                }
        }
        __syncthreads();
    }

    // Epilogue: fp32 stores (float2; columns are even -> 8B aligned)
    #pragma unroll
    for (int mt = 0; mt < 4; mt++) {
        int r0 = bm + wm * 64 + mt * 16 + (l >> 2);
        #pragma unroll
        for (int nt = 0; nt < 4; nt++) {
            int cb = bn + wn * 32 + nt * 8 + (l & 3) * 2;
            float2 v01 = make_float2(acc[mt][nt][0], acc[mt][nt][1]);
            float2 v23 = make_float2(acc[mt][nt][2], acc[mt][nt][3]);
            *(float2*)(C + (size_t)r0 * Ntot + cb) = v01;
            *(float2*)(C + (size_t)(r0 + 8) * Ntot + cb) = v23;
        }
    }
}

// ---------------------------------------------------------------------------
// Per-row softmax(ALPHA*att) + argmax + hard_quantized + bf16 split of sa.
// sa/hardq live in d_out -> only 8B-aligned: scalar/float2 accesses.
__global__ __launch_bounds__(128) void softmax_kernel(
    const float* __restrict__ att, const float* __restrict__ W,
    float* __restrict__ sa, float* __restrict__ argm_out,
    float* __restrict__ hardq)
{
    int row = blockIdx.x;
    int t = threadIdx.x;
    const float* ar = att + (size_t)row * KC;

    float v[8];
    float m = -3.4e38f;
    int mi = 0;
    #pragma unroll
    for (int j = 0; j < 8; j++) {
        int k = t + j * 128;
        float x = ar[k];
        v[j] = x;
        if (x > m) { m = x; mi = k; }
    }

    __shared__ float smx[128];
    __shared__ int   si[128];
    smx[t] = m; si[t] = mi;
    __syncthreads();
    #pragma unroll
    for (int s = 64; s > 0; s >>= 1) {
        if (t < s) {
            float o = smx[t + s]; int oi = si[t + s];
            if (o > smx[t] || (o == smx[t] && oi < si[t])) { smx[t] = o; si[t] = oi; }
        }
        __syncthreads();
    }
    float rowmax = smx[0];
    int arg = si[0];
    __syncthreads();

    float lsum = 0.0f;
    #pragma unroll
    for (int j = 0; j < 8; j++) {
        v[j] = expf(ALPHA * (v[j] - rowmax));
        lsum += v[j];
    }
    smx[t] = lsum;
    __syncthreads();
    #pragma unroll
    for (int s = 64; s > 0; s >>= 1) {
        if (t < s) smx[t] += smx[t + s];
        __syncthreads();
    }
    float inv = 1.0f / smx[0];

    float* sr = sa + (size_t)row * KC;
    size_t rb = (size_t)row * KC;
    #pragma unroll
    for (int j = 0; j < 8; j++) {
        int k = t + j * 128;
        float p = v[j] * inv;
        sr[k] = p;
        __nv_bfloat16 h = __float2bfloat16(p);
        g_sah[rb + k] = h;
        g_sal[rb + k] = __float2bfloat16(p - __bfloat162float(h));
    }

    if (t == 0) {
        argm_out[row] = (float)arg;
        g_rowmax[row] = rowmax;
    }
    // hard_quantized[row,:] = W[arg,:]  (8B-aligned -> float2)
    const float2* wr = (const float2*)(W + (size_t)arg * DD);
    float2* hq = (float2*)(hardq + (size_t)row * DD);
    hq[2 * t + 0] = wr[2 * t + 0];
    hq[2 * t + 1] = wr[2 * t + 1];
}

// ---------------------------------------------------------------------------
// Reduce row maxima (16384 floats) -> g_max_sum. 16 blocks x 1024.
__global__ __launch_bounds__(1024) void rowmax_reduce_kernel()
{
    int i = blockIdx.x * 1024 + threadIdx.x;
    float s = g_rowmax[i];
    #pragma unroll
    for (int o = 16; o > 0; o >>= 1) s += __shfl_xor_sync(0xffffffffu, s, o);
    __shared__ float sm[32];
    int t = threadIdx.x;
    if ((t & 31) == 0) sm[t >> 5] = s;
    __syncthreads();
    if (t == 0) {
        float tot = 0.0f;
        for (int wq = 0; wq < 32; wq++) tot += sm[wq];
        atomicAdd(&g_max_sum, (double)tot);
    }
}

// ---------------------------------------------------------------------------
// Column sums of soft_assign. grid (KC/256, BSZ/1024).
__global__ __launch_bounds__(256) void colsum_kernel(const float* __restrict__ sa)
{
    int k = blockIdx.x * 256 + threadIdx.x;
    int r0 = blockIdx.y * 1024;
    float s = 0.0f;
    for (int r = 0; r < 1024; r++)
        s += sa[(size_t)(r0 + r) * KC + k];
    atomicAdd(&g_avg[k], s);
}

// ---------------------------------------------------------------------------
__global__ __launch_bounds__(256) void mse_kernel(
    const float* __restrict__ q, const float* __restrict__ ln)
{
    const size_t n = (size_t)BSZ * DD;
    size_t i = (size_t)blockIdx.x * blockDim.x + threadIdx.x;
    size_t stride = (size_t)gridDim.x * blockDim.x;
    float s = 0.0f;
    for (; i < n; i += stride) {
        float d = q[i] - ln[i];
        s += d * d;
    }
    #pragma unroll
    for (int o = 16; o > 0; o >>= 1) s += __shfl_xor_sync(0xffffffffu, s, o);
    __shared__ float sm[8];
    int t = threadIdx.x;
    if ((t & 31) == 0) sm[t >> 5] = s;
    __syncthreads();
    if (t == 0) {
        float tot = 0.0f;
        for (int wq = 0; wq < 8; wq++) tot += sm[wq];
        atomicAdd(&g_mse_sum, (double)tot);
    }
}

// ---------------------------------------------------------------------------
__global__ __launch_bounds__(1024) void finalize_kernel(float* __restrict__ out)
{
    int t = threadIdx.x;
    float p = g_avg[t] * (1.0f / (float)BSZ);
    float term = p * logf(p + 1e-10f);
    __shared__ float sm[1024];
    sm[t] = term;
    __syncthreads();
    #pragma unroll
    for (int s = 512; s > 0; s >>= 1) {
        if (t < s) sm[t] += sm[t + s];
        __syncthreads();
    }
    if (t == 0) {
        double mse = g_mse_sum / (double)((size_t)BSZ * DD);
        out[OFF_VQ]  = (float)((1.0 + (double)BETA) * mse);
        out[OFF_ENT] = -sm[0];
        out[OFF_CM]  = (float)(g_max_sum / (double)BSZ);
    }
}

// ---------------------------------------------------------------------------
extern "C" void kernel_launch(void* const* d_in, const int* in_sizes, int n_in,
                              void* d_out, int out_size)
{
    const float* latents = (const float*)d_in[0];   // [B, D]
    const float* emb     = (const float*)d_in[1];   // [K, D]
    float* out = (float*)d_out;

    float* ln  = 0; cudaGetSymbolAddress((void**)&ln,  g_ln);
    float* att = 0; cudaGetSymbolAddress((void**)&att, g_att);
    __nv_bfloat16 *lnh=0,*lnl=0,*cbh=0,*cbl=0,*sah=0,*sal=0,*wth=0,*wtl=0;
    cudaGetSymbolAddress((void**)&lnh, g_lnh);
    cudaGetSymbolAddress((void**)&lnl, g_lnl);
    cudaGetSymbolAddress((void**)&cbh, g_cbh);
    cudaGetSymbolAddress((void**)&cbl, g_cbl);
    cudaGetSymbolAddress((void**)&sah, g_sah);
    cudaGetSymbolAddress((void**)&sal, g_sal);
    cudaGetSymbolAddress((void**)&wth, g_wth);
    cudaGetSymbolAddress((void**)&wtl, g_wtl);

    cudaFuncSetAttribute(hmma_gemm_kernel,
                         cudaFuncAttributeMaxDynamicSharedMemorySize, GSMEM_BYTES);

    float* q_out   = out + OFF_Q;
    float* arg_out = out + OFF_ARG;
    float* hq_out  = out + OFF_HQ;
    float* sa_out  = out + OFF_SA;

    init_kernel<<<1, 1024>>>();
    l2norm_split_kernel<false><<<KC, 128>>>(emb, 0, cbh, cbl);
    l2norm_split_kernel<true><<<BSZ, 128>>>(latents, ln, lnh, lnl);
    {
        dim3 grid(KC / 32, DD / 32);
        transpose_split_kernel<<<grid, 1024>>>(emb, wth, wtl);
    }

    // attention = ln [B,512] * cbn [1024,512]^T  -> [B,1024]
    {
        dim3 grid(KC / 128, BSZ / 128);
        hmma_gemm_kernel<<<grid, GTHREADS, GSMEM_BYTES>>>(lnh, lnl, cbh, cbl, att, KC, DD);
    }

    softmax_kernel<<<BSZ, 128>>>(att, emb, sa_out, arg_out, hq_out);
    rowmax_reduce_kernel<<<BSZ / 1024, 1024>>>();
    {
        dim3 grid(KC / 256, BSZ / 1024);
        colsum_kernel<<<grid, 256>>>(sa_out);
    }

    // quantized = sa [B,1024] * Wt [512,1024]^T -> [B,512]
    {
        dim3 grid(DD / 128, BSZ / 128);
        hmma_gemm_kernel<<<grid, GTHREADS, GSMEM_BYTES>>>(sah, sal, wth, wtl, q_out, DD, KC);
    }

    mse_kernel<<<2048, 256>>>(q_out, ln);
    finalize_kernel<<<1, 1024>>>(out);
}

// round 8
// speedup vs baseline: 2.3346x; 1.1140x over previous
#include <cuda_runtime.h>
#include <cuda_bf16.h>
#include <cuda_fp16.h>
#include <math.h>
#include <stdint.h>

// Problem constants
#define BSZ 16384
#define DD  512
#define KC  1024
#define ALPHA 10.0f
#define BETA  0.25f

// Output layout (concatenated fp32):
//  quantized [B,D], vq_loss [1], entropy_vq [1], argm [B], hard_quantized [B,D],
//  soft_assign [B,K], cluster_metric [1]
// OFF_HQ / OFF_SA are == 2 mod 4 floats -> only 8-byte aligned.
#define OFF_Q   ((size_t)0)
#define OFF_VQ  ((size_t)(BSZ*DD))
#define OFF_ENT (OFF_VQ + 1)
#define OFF_ARG (OFF_ENT + 1)
#define OFF_HQ  (OFF_ARG + BSZ)
#define OFF_SA  (OFF_HQ + (size_t)BSZ*DD)
#define OFF_CM  (OFF_SA + (size_t)BSZ*KC)

// ---------------------------------------------------------------------------
// Scratch (device globals; no allocation allowed).
__device__ float  g_ln [(size_t)BSZ * DD];   // normalized latents fp32
__device__ float  g_att[(size_t)BSZ * KC];   // attention logits
__device__ __align__(128) __nv_bfloat16 g_lnh[(size_t)BSZ * DD];
__device__ __align__(128) __nv_bfloat16 g_lnl[(size_t)BSZ * DD];
__device__ __align__(128) __nv_bfloat16 g_cbh[(size_t)KC * DD];
__device__ __align__(128) __nv_bfloat16 g_cbl[(size_t)KC * DD];
__device__ __align__(128) __half g_sah[(size_t)BSZ * KC];   // sa hi (fp16)
__device__ __align__(128) __half g_sal[(size_t)BSZ * KC];   // sa lo (fp16)
__device__ __align__(128) __half g_wth[(size_t)DD * KC];    // W^T fp16 [D,K]
__device__ float  g_rowmax[BSZ];
__device__ float  g_avg[KC];
__device__ double g_mse_sum;

// ---------------------------------------------------------------------------
// Baseline-PTX helpers (valid on compute_103): cp.async, ldmatrix, mma.sync
__device__ __forceinline__ uint32_t smem_u32(const void* p) {
    return (uint32_t)__cvta_generic_to_shared(p);
}
__device__ __forceinline__ void cp_async16(uint32_t saddr, const void* gaddr) {
    asm volatile("cp.async.cg.shared.global [%0], [%1], 16;"
                 :: "r"(saddr), "l"(gaddr) : "memory");
}
__device__ __forceinline__ void cp_commit() {
    asm volatile("cp.async.commit_group;" ::: "memory");
}
__device__ __forceinline__ void cp_wait0() {
    asm volatile("cp.async.wait_group 0;" ::: "memory");
}
__device__ __forceinline__ void cp_wait1() {
    asm volatile("cp.async.wait_group 1;" ::: "memory");
}
__device__ __forceinline__ void ldsm_x4(uint32_t& r0, uint32_t& r1,
                                        uint32_t& r2, uint32_t& r3, uint32_t a) {
    asm volatile("ldmatrix.sync.aligned.m8n8.x4.shared.b16 {%0,%1,%2,%3}, [%4];"
                 : "=r"(r0), "=r"(r1), "=r"(r2), "=r"(r3) : "r"(a));
}
// Typed mma.sync m16n8k16 (row.col, fp32 accum)
template<typename T>
__device__ __forceinline__ void mma_tc(float* c, const uint32_t* a, const uint32_t* b);
template<>
__device__ __forceinline__ void mma_tc<__nv_bfloat16>(float* c, const uint32_t* a,
                                                      const uint32_t* b) {
    asm volatile(
        "mma.sync.aligned.m16n8k16.row.col.f32.bf16.bf16.f32 "
        "{%0,%1,%2,%3}, {%4,%5,%6,%7}, {%8,%9}, {%0,%1,%2,%3};"
        : "+f"(c[0]), "+f"(c[1]), "+f"(c[2]), "+f"(c[3])
        : "r"(a[0]), "r"(a[1]), "r"(a[2]), "r"(a[3]), "r"(b[0]), "r"(b[1]));
}
template<>
__device__ __forceinline__ void mma_tc<__half>(float* c, const uint32_t* a,
                                               const uint32_t* b) {
    asm volatile(
        "mma.sync.aligned.m16n8k16.row.col.f32.f16.f16.f32 "
        "{%0,%1,%2,%3}, {%4,%5,%6,%7}, {%8,%9}, {%0,%1,%2,%3};"
        : "+f"(c[0]), "+f"(c[1]), "+f"(c[2]), "+f"(c[3])
        : "r"(a[0]), "r"(a[1]), "r"(a[2]), "r"(a[3]), "r"(b[0]), "r"(b[1]));
}

// ---------------------------------------------------------------------------
__global__ void init_kernel() {
    int t = threadIdx.x;
    if (t < KC) g_avg[t] = 0.0f;
    if (t == 0) g_mse_sum = 0.0;
}

// ---------------------------------------------------------------------------
// Row L2 normalize + bf16 hi/lo split. One block (128 thr) per row of 512.
template <bool WF32>
__global__ __launch_bounds__(128) void l2norm_split_kernel(
    const float* __restrict__ x, float* __restrict__ y,
    __nv_bfloat16* __restrict__ yh, __nv_bfloat16* __restrict__ yl)
{
    int r = blockIdx.x;
    int t = threadIdx.x;
    const float4* xr = (const float4*)(x + (size_t)r * DD);
    float4 v = xr[t];
    float s = v.x * v.x + v.y * v.y + v.z * v.z + v.w * v.w;
    #pragma unroll
    for (int o = 16; o > 0; o >>= 1) s += __shfl_xor_sync(0xffffffffu, s, o);
    __shared__ float sm[4];
    if ((t & 31) == 0) sm[t >> 5] = s;
    __syncthreads();
    float tot = sm[0] + sm[1] + sm[2] + sm[3];
    float inv = 1.0f / fmaxf(sqrtf(tot), 1e-12f);
    float o4[4] = { v.x * inv, v.y * inv, v.z * inv, v.w * inv };
    if (WF32) {
        ((float4*)(y + (size_t)r * DD))[t] = make_float4(o4[0], o4[1], o4[2], o4[3]);
    }
    size_t base = (size_t)r * DD + t * 4;
    #pragma unroll
    for (int j = 0; j < 4; j++) {
        __nv_bfloat16 h = __float2bfloat16(o4[j]);
        yh[base + j] = h;
        yl[base + j] = __float2bfloat16(o4[j] - __bfloat162float(h));
    }
}

// ---------------------------------------------------------------------------
// W [KC, DD] -> Wt fp16 [DD, KC]
__global__ __launch_bounds__(1024) void transpose_h_kernel(
    const float* __restrict__ W, __half* __restrict__ th)
{
    __shared__ float tile[32][33];
    int k0 = blockIdx.x * 32, d0 = blockIdx.y * 32;
    int tx = threadIdx.x & 31, ty = threadIdx.x >> 5;
    tile[ty][tx] = W[(size_t)(k0 + ty) * DD + d0 + tx];
    __syncthreads();
    float v = tile[tx][ty];
    th[(size_t)(d0 + ty) * KC + k0 + tx] = __float2half_rn(v);
}

// ---------------------------------------------------------------------------
// HMMA GEMM, CTA tile 128x128, BK=32, 8 warps (2Mx4N), warp tile 64x32.
// NTILES==4 (bf16x3): C = Ah*Bh + Ah*Bl + Al*Bh   (tiles Ah,Al,Bh,Bl)
// NTILES==3 (fp16x2): C = Ah*Bh + Al*Bh           (tiles Ah,Al,Bh)
// FUSE: accumulate sum((C - Lref)^2) into g_mse_sum (one atomic per CTA).
// Double-buffered cp.async smem; rows padded to 80B (conflict-free ldmatrix).
#define GTHREADS 256
#define ROWB   80
#define TILE_B (128 * ROWB)          // 10240 bytes per 128x32 bf16/fp16 tile

template<typename VT, int NTILES, bool FUSE>
__global__ __launch_bounds__(GTHREADS, 1) void hmma_gemm_kernel(
    const VT* __restrict__ Ah, const VT* __restrict__ Al,
    const VT* __restrict__ Bh, const VT* __restrict__ Bl,
    float* __restrict__ C, const float* __restrict__ Lref, int Ntot, int Kd)
{
    constexpr int STAGE_B = NTILES * TILE_B;
    extern __shared__ char smraw[];
    int tid = threadIdx.x;
    int w = tid >> 5, l = tid & 31;
    int wm = w & 1, wn = w >> 1;
    int bm = blockIdx.y * 128;
    int bn = blockIdx.x * 128;

    const VT* gtile[NTILES];
    gtile[0] = Ah + (size_t)bm * Kd;
    gtile[1] = Al + (size_t)bm * Kd;
    gtile[2] = Bh + (size_t)bn * Kd;
    if constexpr (NTILES == 4) gtile[3] = Bl + (size_t)bn * Kd;

    uint32_t sbase = smem_u32(smraw);

    auto load_stage = [&](int kc, int st) {
        uint32_t sb = sbase + st * STAGE_B;
        #pragma unroll
        for (int it = 0; it < 2 * NTILES; it++) {
            int g = it * GTHREADS + tid;
            int tile = g >> 9;
            int c = g & 511;
            int row = c >> 2;
            int col = c & 3;
            const char* src = (const char*)(gtile[tile] + (size_t)row * Kd + kc * 32)
                              + col * 16;
            cp_async16(sb + tile * TILE_B + row * ROWB + col * 16, src);
        }
        cp_commit();
    };

    float acc[4][4][4];
    #pragma unroll
    for (int i = 0; i < 4; i++)
        #pragma unroll
        for (int j = 0; j < 4; j++)
            #pragma unroll
            for (int q = 0; q < 4; q++) acc[i][j][q] = 0.0f;

    int nch = Kd >> 5;
    load_stage(0, 0);

    for (int kc = 0; kc < nch; kc++) {
        int st = kc & 1;
        if (kc + 1 < nch) { load_stage(kc + 1, st ^ 1); cp_wait1(); }
        else              { cp_wait0(); }
        __syncthreads();

        uint32_t ahb = sbase + st * STAGE_B + 0 * TILE_B;
        uint32_t alb = sbase + st * STAGE_B + 1 * TILE_B;
        uint32_t bhb = sbase + st * STAGE_B + 2 * TILE_B;
        uint32_t blb = sbase + st * STAGE_B + 3 * TILE_B;

        int ldrow = l & 15;
        int ldcol = (l >> 4) * 16;

        #pragma unroll
        for (int kk = 0; kk < 2; kk++) {
            int kb = kk * 32 + ldcol;
            uint32_t a_h[4][4], a_l[4][4];
            #pragma unroll
            for (int mt = 0; mt < 4; mt++) {
                uint32_t off = (uint32_t)(wm * 64 + mt * 16 + ldrow) * ROWB + kb;
                ldsm_x4(a_h[mt][0], a_h[mt][1], a_h[mt][2], a_h[mt][3], ahb + off);
                ldsm_x4(a_l[mt][0], a_l[mt][1], a_l[mt][2], a_l[mt][3], alb + off);
            }
            uint32_t b_h[4][2], b_l[4][2];
            #pragma unroll
            for (int np = 0; np < 2; np++) {
                uint32_t off = (uint32_t)(wn * 32 + np * 16 + ldrow) * ROWB + kb;
                uint32_t r0, r1, r2, r3;
                ldsm_x4(r0, r1, r2, r3, bhb + off);
                b_h[2 * np][0] = r0; b_h[2 * np][1] = r2;
                b_h[2 * np + 1][0] = r1; b_h[2 * np + 1][1] = r3;
                if constexpr (NTILES == 4) {
                    ldsm_x4(r0, r1, r2, r3, blb + off);
                    b_l[2 * np][0] = r0; b_l[2 * np][1] = r2;
                    b_l[2 * np + 1][0] = r1; b_l[2 * np + 1][1] = r3;
                }
            }
            #pragma unroll
            for (int mt = 0; mt < 4; mt++)
                #pragma unroll
                for (int nt = 0; nt < 4; nt++) {
                    mma_tc<VT>(acc[mt][nt], a_h[mt], b_h[nt]);
                    if constexpr (NTILES == 4)
                        mma_tc<VT>(acc[mt][nt], a_h[mt], b_l[nt]);
                    mma_tc<VT>(acc[mt][nt], a_l[mt], b_h[nt]);
                }
        }
        __syncthreads();
    }

    // Epilogue: fp32 float2 stores (+ optional fused (C-Lref)^2 accumulation)
    float msum = 0.0f;
    #pragma unroll
    for (int mt = 0; mt < 4; mt++) {
        int r0 = bm + wm * 64 + mt * 16 + (l >> 2);
        #pragma unroll
        for (int nt = 0; nt < 4; nt++) {
            int cb = bn + wn * 32 + nt * 8 + (l & 3) * 2;
            float2 v01 = make_float2(acc[mt][nt][0], acc[mt][nt][1]);
            float2 v23 = make_float2(acc[mt][nt][2], acc[mt][nt][3]);
            *(float2*)(C + (size_t)r0 * Ntot + cb) = v01;
            *(float2*)(C + (size_t)(r0 + 8) * Ntot + cb) = v23;
            if constexpr (FUSE) {
                float2 l01 = *(const float2*)(Lref + (size_t)r0 * Ntot + cb);
                float2 l23 = *(const float2*)(Lref + (size_t)(r0 + 8) * Ntot + cb);
                float d0 = v01.x - l01.x, d1 = v01.y - l01.y;
                float d2 = v23.x - l23.x, d3 = v23.y - l23.y;
                msum += d0 * d0 + d1 * d1 + d2 * d2 + d3 * d3;
            }
        }
    }
    if constexpr (FUSE) {
        #pragma unroll
        for (int o = 16; o > 0; o >>= 1)
            msum += __shfl_xor_sync(0xffffffffu, msum, o);
        __shared__ float smm[8];
        if (l == 0) smm[w] = msum;
        __syncthreads();
        if (tid == 0) {
            float tot = 0.0f;
            #pragma unroll
            for (int q = 0; q < 8; q++) tot += smm[q];
            atomicAdd(&g_mse_sum, (double)tot);
        }
    }
}

// ---------------------------------------------------------------------------
// Per-row softmax(ALPHA*att) + argmax + hard_quantized + fp16 split of sa.
// sa/hardq live in d_out -> only 8B-aligned: scalar/float2 accesses.
__global__ __launch_bounds__(128) void softmax_kernel(
    const float* __restrict__ att, const float* __restrict__ W,
    float* __restrict__ sa, float* __restrict__ argm_out,
    float* __restrict__ hardq)
{
    int row = blockIdx.x;
    int t = threadIdx.x;
    const float* ar = att + (size_t)row * KC;

    float v[8];
    float m = -3.4e38f;
    int mi = 0;
    #pragma unroll
    for (int j = 0; j < 8; j++) {
        int k = t + j * 128;
        float x = ar[k];
        v[j] = x;
        if (x > m) { m = x; mi = k; }
    }

    __shared__ float smx[128];
    __shared__ int   si[128];
    smx[t] = m; si[t] = mi;
    __syncthreads();
    #pragma unroll
    for (int s = 64; s > 0; s >>= 1) {
        if (t < s) {
            float o = smx[t + s]; int oi = si[t + s];
            if (o > smx[t] || (o == smx[t] && oi < si[t])) { smx[t] = o; si[t] = oi; }
        }
        __syncthreads();
    }
    float rowmax = smx[0];
    int arg = si[0];
    __syncthreads();

    float lsum = 0.0f;
    #pragma unroll
    for (int j = 0; j < 8; j++) {
        v[j] = expf(ALPHA * (v[j] - rowmax));
        lsum += v[j];
    }
    smx[t] = lsum;
    __syncthreads();
    #pragma unroll
    for (int s = 64; s > 0; s >>= 1) {
        if (t < s) smx[t] += smx[t + s];
        __syncthreads();
    }
    float inv = 1.0f / smx[0];

    float* sr = sa + (size_t)row * KC;
    size_t rb = (size_t)row * KC;
    #pragma unroll
    for (int j = 0; j < 8; j++) {
        int k = t + j * 128;
        float p = v[j] * inv;
        sr[k] = p;
        __half h = __float2half_rn(p);
        g_sah[rb + k] = h;
        g_sal[rb + k] = __float2half_rn(p - __half2float(h));
    }

    if (t == 0) {
        argm_out[row] = (float)arg;
        g_rowmax[row] = rowmax;
    }
    // hard_quantized[row,:] = W[arg,:]  (8B-aligned -> float2)
    const float2* wr = (const float2*)(W + (size_t)arg * DD);
    float2* hq = (float2*)(hardq + (size_t)row * DD);
    hq[2 * t + 0] = wr[2 * t + 0];
    hq[2 * t + 1] = wr[2 * t + 1];
}

// ---------------------------------------------------------------------------
// Column sums of soft_assign. grid (KC/256, BSZ/1024).
__global__ __launch_bounds__(256) void colsum_kernel(const float* __restrict__ sa)
{
    int k = blockIdx.x * 256 + threadIdx.x;
    int r0 = blockIdx.y * 1024;
    float s = 0.0f;
    for (int r = 0; r < 1024; r++)
        s += sa[(size_t)(r0 + r) * KC + k];
    atomicAdd(&g_avg[k], s);
}

// ---------------------------------------------------------------------------
// Final scalars: vq_loss (from fused mse), entropy_vq, cluster_metric (rowmax).
__global__ __launch_bounds__(1024) void finalize_kernel(float* __restrict__ out)
{
    int t = threadIdx.x;
    float p = g_avg[t] * (1.0f / (float)BSZ);
    float ent = p * logf(p + 1e-10f);
    float rmx = 0.0f;
    #pragma unroll
    for (int j = 0; j < 16; j++) rmx += g_rowmax[t + j * 1024];
    __shared__ float se[1024];
    __shared__ float sr[1024];
    se[t] = ent; sr[t] = rmx;
    __syncthreads();
    #pragma unroll
    for (int s = 512; s > 0; s >>= 1) {
        if (t < s) { se[t] += se[t + s]; sr[t] += sr[t + s]; }
        __syncthreads();
    }
    if (t == 0) {
        double mse = g_mse_sum / (double)((size_t)BSZ * DD);
        out[OFF_VQ]  = (float)((1.0 + (double)BETA) * mse);
        out[OFF_ENT] = -se[0];
        out[OFF_CM]  = (float)((double)sr[0] / (double)BSZ);
    }
}

// ---------------------------------------------------------------------------
extern "C" void kernel_launch(void* const* d_in, const int* in_sizes, int n_in,
                              void* d_out, int out_size)
{
    const float* latents = (const float*)d_in[0];   // [B, D]
    const float* emb     = (const float*)d_in[1];   // [K, D]
    float* out = (float*)d_out;

    float* ln  = 0; cudaGetSymbolAddress((void**)&ln,  g_ln);
    float* att = 0; cudaGetSymbolAddress((void**)&att, g_att);
    __nv_bfloat16 *lnh=0,*lnl=0,*cbh=0,*cbl=0;
    __half *sah=0,*sal=0,*wth=0;
    cudaGetSymbolAddress((void**)&lnh, g_lnh);
    cudaGetSymbolAddress((void**)&lnl, g_lnl);
    cudaGetSymbolAddress((void**)&cbh, g_cbh);
    cudaGetSymbolAddress((void**)&cbl, g_cbl);
    cudaGetSymbolAddress((void**)&sah, g_sah);
    cudaGetSymbolAddress((void**)&sal, g_sal);
    cudaGetSymbolAddress((void**)&wth, g_wth);

    cudaFuncSetAttribute((const void*)hmma_gemm_kernel<__nv_bfloat16, 4, false>,
                         cudaFuncAttributeMaxDynamicSharedMemorySize, 2 * 4 * TILE_B);
    cudaFuncSetAttribute((const void*)hmma_gemm_kernel<__half, 3, true>,
                         cudaFuncAttributeMaxDynamicSharedMemorySize, 2 * 3 * TILE_B);

    float* q_out   = out + OFF_Q;
    float* arg_out = out + OFF_ARG;
    float* hq_out  = out + OFF_HQ;
    float* sa_out  = out + OFF_SA;

    init_kernel<<<1, 1024>>>();
    l2norm_split_kernel<false><<<KC, 128>>>(emb, 0, cbh, cbl);
    l2norm_split_kernel<true><<<BSZ, 128>>>(latents, ln, lnh, lnl);
    {
        dim3 grid(KC / 32, DD / 32);
        transpose_h_kernel<<<grid, 1024>>>(emb, wth);
    }

    // attention = ln [B,512] * cbn [1024,512]^T  (bf16 x3, fp32 acc)
    {
        dim3 grid(KC / 128, BSZ / 128);
        hmma_gemm_kernel<__nv_bfloat16, 4, false>
            <<<grid, GTHREADS, 2 * 4 * TILE_B>>>(lnh, lnl, cbh, cbl, att, 0, KC, DD);
    }

    softmax_kernel<<<BSZ, 128>>>(att, emb, sa_out, arg_out, hq_out);
    {
        dim3 grid(KC / 256, BSZ / 1024);
        colsum_kernel<<<grid, 256>>>(sa_out);
    }

    // quantized = sa [B,1024] * Wt [512,1024]^T  (fp16 x2, fp32 acc, fused MSE)
    {
        dim3 grid(DD / 128, BSZ / 128);
        hmma_gemm_kernel<__half, 3, true>
            <<<grid, GTHREADS, 2 * 3 * TILE_B>>>(sah, sal, wth, 0, q_out, ln, DD, KC);
    }

    finalize_kernel<<<1, 1024>>>(out);
}

// round 9
// speedup vs baseline: 2.7217x; 1.1658x over previous
#include <cuda_runtime.h>
#include <cuda_bf16.h>
#include <cuda_fp16.h>
#include <math.h>
#include <stdint.h>

// Problem constants
#define BSZ 16384
#define DD  512
#define KC  1024
#define ALPHA 10.0f
#define BETA  0.25f

// Output layout (concatenated fp32):
//  quantized [B,D], vq_loss [1], entropy_vq [1], argm [B], hard_quantized [B,D],
//  soft_assign [B,K], cluster_metric [1]
// OFF_HQ / OFF_SA are == 2 mod 4 floats -> only 8-byte aligned.
#define OFF_Q   ((size_t)0)
#define OFF_VQ  ((size_t)(BSZ*DD))
#define OFF_ENT (OFF_VQ + 1)
#define OFF_ARG (OFF_ENT + 1)
#define OFF_HQ  (OFF_ARG + BSZ)
#define OFF_SA  (OFF_HQ + (size_t)BSZ*DD)
#define OFF_CM  (OFF_SA + (size_t)BSZ*KC)

// ---------------------------------------------------------------------------
// Scratch (device globals; no allocation allowed).
__device__ float  g_ln [(size_t)BSZ * DD];   // normalized latents fp32
__device__ float  g_att[(size_t)BSZ * KC];   // attention logits
__device__ __align__(128) __nv_bfloat16 g_lnh[(size_t)BSZ * DD];
__device__ __align__(128) __nv_bfloat16 g_lnl[(size_t)BSZ * DD];
__device__ __align__(128) __nv_bfloat16 g_cbh[(size_t)KC * DD];
__device__ __align__(128) __nv_bfloat16 g_cbl[(size_t)KC * DD];
__device__ __align__(128) __half g_sah[(size_t)BSZ * KC];   // sa (fp16)
__device__ __align__(128) __half g_wth[(size_t)DD * KC];    // W^T fp16 [D,K]
__device__ float  g_rowmax[BSZ];
__device__ float  g_avg[KC];
__device__ double g_mse_sum;

// ---------------------------------------------------------------------------
// Baseline-PTX helpers (valid on compute_103): cp.async, ldmatrix, mma.sync
__device__ __forceinline__ uint32_t smem_u32(const void* p) {
    return (uint32_t)__cvta_generic_to_shared(p);
}
__device__ __forceinline__ void cp_async16(uint32_t saddr, const void* gaddr) {
    asm volatile("cp.async.cg.shared.global [%0], [%1], 16;"
                 :: "r"(saddr), "l"(gaddr) : "memory");
}
__device__ __forceinline__ void cp_commit() {
    asm volatile("cp.async.commit_group;" ::: "memory");
}
__device__ __forceinline__ void cp_wait0() {
    asm volatile("cp.async.wait_group 0;" ::: "memory");
}
__device__ __forceinline__ void cp_wait1() {
    asm volatile("cp.async.wait_group 1;" ::: "memory");
}
__device__ __forceinline__ void ldsm_x4(uint32_t& r0, uint32_t& r1,
                                        uint32_t& r2, uint32_t& r3, uint32_t a) {
    asm volatile("ldmatrix.sync.aligned.m8n8.x4.shared.b16 {%0,%1,%2,%3}, [%4];"
                 : "=r"(r0), "=r"(r1), "=r"(r2), "=r"(r3) : "r"(a));
}
// Typed mma.sync m16n8k16 (row.col, fp32 accum)
template<typename T>
__device__ __forceinline__ void mma_tc(float* c, const uint32_t* a, const uint32_t* b);
template<>
__device__ __forceinline__ void mma_tc<__nv_bfloat16>(float* c, const uint32_t* a,
                                                      const uint32_t* b) {
    asm volatile(
        "mma.sync.aligned.m16n8k16.row.col.f32.bf16.bf16.f32 "
        "{%0,%1,%2,%3}, {%4,%5,%6,%7}, {%8,%9}, {%0,%1,%2,%3};"
        : "+f"(c[0]), "+f"(c[1]), "+f"(c[2]), "+f"(c[3])
        : "r"(a[0]), "r"(a[1]), "r"(a[2]), "r"(a[3]), "r"(b[0]), "r"(b[1]));
}
template<>
__device__ __forceinline__ void mma_tc<__half>(float* c, const uint32_t* a,
                                               const uint32_t* b) {
    asm volatile(
        "mma.sync.aligned.m16n8k16.row.col.f32.f16.f16.f32 "
        "{%0,%1,%2,%3}, {%4,%5,%6,%7}, {%8,%9}, {%0,%1,%2,%3};"
        : "+f"(c[0]), "+f"(c[1]), "+f"(c[2]), "+f"(c[3])
        : "r"(a[0]), "r"(a[1]), "r"(a[2]), "r"(a[3]), "r"(b[0]), "r"(b[1]));
}

// ---------------------------------------------------------------------------
__global__ void init_kernel() {
    int t = threadIdx.x;
    if (t < KC) g_avg[t] = 0.0f;
    if (t == 0) g_mse_sum = 0.0;
}

// ---------------------------------------------------------------------------
// Row L2 normalize + bf16 hi/lo split. One block (128 thr) per row of 512.
template <bool WF32>
__global__ __launch_bounds__(128) void l2norm_split_kernel(
    const float* __restrict__ x, float* __restrict__ y,
    __nv_bfloat16* __restrict__ yh, __nv_bfloat16* __restrict__ yl)
{
    int r = blockIdx.x;
    int t = threadIdx.x;
    const float4* xr = (const float4*)(x + (size_t)r * DD);
    float4 v = xr[t];
    float s = v.x * v.x + v.y * v.y + v.z * v.z + v.w * v.w;
    #pragma unroll
    for (int o = 16; o > 0; o >>= 1) s += __shfl_xor_sync(0xffffffffu, s, o);
    __shared__ float sm[4];
    if ((t & 31) == 0) sm[t >> 5] = s;
    __syncthreads();
    float tot = sm[0] + sm[1] + sm[2] + sm[3];
    float inv = 1.0f / fmaxf(sqrtf(tot), 1e-12f);
    float o4[4] = { v.x * inv, v.y * inv, v.z * inv, v.w * inv };
    if (WF32) {
        ((float4*)(y + (size_t)r * DD))[t] = make_float4(o4[0], o4[1], o4[2], o4[3]);
    }
    size_t base = (size_t)r * DD + t * 4;
    #pragma unroll
    for (int j = 0; j < 4; j++) {
        __nv_bfloat16 h = __float2bfloat16(o4[j]);
        yh[base + j] = h;
        yl[base + j] = __float2bfloat16(o4[j] - __bfloat162float(h));
    }
}

// ---------------------------------------------------------------------------
// W [KC, DD] -> Wt fp16 [DD, KC]
__global__ __launch_bounds__(1024) void transpose_h_kernel(
    const float* __restrict__ W, __half* __restrict__ th)
{
    __shared__ float tile[32][33];
    int k0 = blockIdx.x * 32, d0 = blockIdx.y * 32;
    int tx = threadIdx.x & 31, ty = threadIdx.x >> 5;
    tile[ty][tx] = W[(size_t)(k0 + ty) * DD + d0 + tx];
    __syncthreads();
    float v = tile[tx][ty];
    th[(size_t)(d0 + ty) * KC + k0 + tx] = __float2half_rn(v);
}

// ---------------------------------------------------------------------------
// HMMA GEMM, CTA tile 128x128, BK=32, 8 warps (2Mx4N), warp tile 64x32.
// NTILES==4 (bf16x3): C = Ah*Bh + Ah*Bl + Al*Bh  (tiles Ah,Al,Bh,Bl)
// NTILES==2 (1-term): C = Ah*Bh                  (tiles Ah,Bh)
// FUSE: accumulate sum((C - Lref)^2) into g_mse_sum (one atomic per CTA).
// Double-buffered cp.async smem; rows padded to 80B (conflict-free ldmatrix).
#define GTHREADS 256
#define ROWB   80
#define TILE_B (128 * ROWB)          // 10240 bytes per 128x32 bf16/fp16 tile

template<typename VT, int NTILES, bool FUSE>
__global__ __launch_bounds__(GTHREADS, 1) void hmma_gemm_kernel(
    const VT* __restrict__ Ah, const VT* __restrict__ Al,
    const VT* __restrict__ Bh, const VT* __restrict__ Bl,
    float* __restrict__ C, const float* __restrict__ Lref, int Ntot, int Kd)
{
    constexpr int STAGE_B = NTILES * TILE_B;
    constexpr int BIDX = (NTILES == 2) ? 1 : 2;
    extern __shared__ char smraw[];
    int tid = threadIdx.x;
    int w = tid >> 5, l = tid & 31;
    int wm = w & 1, wn = w >> 1;
    int bm = blockIdx.y * 128;
    int bn = blockIdx.x * 128;

    const VT* gtile[NTILES];
    gtile[0] = Ah + (size_t)bm * Kd;
    if constexpr (NTILES == 2) {
        gtile[1] = Bh + (size_t)bn * Kd;
    } else {
        gtile[1] = Al + (size_t)bm * Kd;
        gtile[2] = Bh + (size_t)bn * Kd;
        if constexpr (NTILES == 4) gtile[3] = Bl + (size_t)bn * Kd;
    }

    uint32_t sbase = smem_u32(smraw);

    auto load_stage = [&](int kc, int st) {
        uint32_t sb = sbase + st * STAGE_B;
        #pragma unroll
        for (int it = 0; it < 2 * NTILES; it++) {
            int g = it * GTHREADS + tid;
            int tile = g >> 9;
            int c = g & 511;
            int row = c >> 2;
            int col = c & 3;
            const char* src = (const char*)(gtile[tile] + (size_t)row * Kd + kc * 32)
                              + col * 16;
            cp_async16(sb + tile * TILE_B + row * ROWB + col * 16, src);
        }
        cp_commit();
    };

    float acc[4][4][4];
    #pragma unroll
    for (int i = 0; i < 4; i++)
        #pragma unroll
        for (int j = 0; j < 4; j++)
            #pragma unroll
            for (int q = 0; q < 4; q++) acc[i][j][q] = 0.0f;

    int nch = Kd >> 5;
    load_stage(0, 0);

    for (int kc = 0; kc < nch; kc++) {
        int st = kc & 1;
        if (kc + 1 < nch) { load_stage(kc + 1, st ^ 1); cp_wait1(); }
        else              { cp_wait0(); }
        __syncthreads();

        uint32_t ahb = sbase + st * STAGE_B + 0 * TILE_B;
        uint32_t alb = sbase + st * STAGE_B + 1 * TILE_B;
        uint32_t bhb = sbase + st * STAGE_B + BIDX * TILE_B;
        uint32_t blb = sbase + st * STAGE_B + 3 * TILE_B;

        int ldrow = l & 15;
        int ldcol = (l >> 4) * 16;

        #pragma unroll
        for (int kk = 0; kk < 2; kk++) {
            int kb = kk * 32 + ldcol;
            uint32_t a_h[4][4], a_l[4][4];
            #pragma unroll
            for (int mt = 0; mt < 4; mt++) {
                uint32_t off = (uint32_t)(wm * 64 + mt * 16 + ldrow) * ROWB + kb;
                ldsm_x4(a_h[mt][0], a_h[mt][1], a_h[mt][2], a_h[mt][3], ahb + off);
                if constexpr (NTILES >= 3)
                    ldsm_x4(a_l[mt][0], a_l[mt][1], a_l[mt][2], a_l[mt][3], alb + off);
            }
            uint32_t b_h[4][2], b_l[4][2];
            #pragma unroll
            for (int np = 0; np < 2; np++) {
                uint32_t off = (uint32_t)(wn * 32 + np * 16 + ldrow) * ROWB + kb;
                uint32_t r0, r1, r2, r3;
                ldsm_x4(r0, r1, r2, r3, bhb + off);
                b_h[2 * np][0] = r0; b_h[2 * np][1] = r2;
                b_h[2 * np + 1][0] = r1; b_h[2 * np + 1][1] = r3;
                if constexpr (NTILES == 4) {
                    ldsm_x4(r0, r1, r2, r3, blb + off);
                    b_l[2 * np][0] = r0; b_l[2 * np][1] = r2;
                    b_l[2 * np + 1][0] = r1; b_l[2 * np + 1][1] = r3;
                }
            }
            #pragma unroll
            for (int mt = 0; mt < 4; mt++)
                #pragma unroll
                for (int nt = 0; nt < 4; nt++) {
                    mma_tc<VT>(acc[mt][nt], a_h[mt], b_h[nt]);
                    if constexpr (NTILES == 4)
                        mma_tc<VT>(acc[mt][nt], a_h[mt], b_l[nt]);
                    if constexpr (NTILES >= 3)
                        mma_tc<VT>(acc[mt][nt], a_l[mt], b_h[nt]);
                }
        }
        __syncthreads();
    }

    // Epilogue: fp32 float2 stores (+ optional fused (C-Lref)^2 accumulation)
    float msum = 0.0f;
    #pragma unroll
    for (int mt = 0; mt < 4; mt++) {
        int r0 = bm + wm * 64 + mt * 16 + (l >> 2);
        #pragma unroll
        for (int nt = 0; nt < 4; nt++) {
            int cb = bn + wn * 32 + nt * 8 + (l & 3) * 2;
            float2 v01 = make_float2(acc[mt][nt][0], acc[mt][nt][1]);
            float2 v23 = make_float2(acc[mt][nt][2], acc[mt][nt][3]);
            *(float2*)(C + (size_t)r0 * Ntot + cb) = v01;
            *(float2*)(C + (size_t)(r0 + 8) * Ntot + cb) = v23;
            if constexpr (FUSE) {
                float2 l01 = *(const float2*)(Lref + (size_t)r0 * Ntot + cb);
                float2 l23 = *(const float2*)(Lref + (size_t)(r0 + 8) * Ntot + cb);
                float d0 = v01.x - l01.x, d1 = v01.y - l01.y;
                float d2 = v23.x - l23.x, d3 = v23.y - l23.y;
                msum += d0 * d0 + d1 * d1 + d2 * d2 + d3 * d3;
            }
        }
    }
    if constexpr (FUSE) {
        #pragma unroll
        for (int o = 16; o > 0; o >>= 1)
            msum += __shfl_xor_sync(0xffffffffu, msum, o);
        __shared__ float smm[8];
        if (l == 0) smm[w] = msum;
        __syncthreads();
        if (tid == 0) {
            float tot = 0.0f;
            #pragma unroll
            for (int q = 0; q < 8; q++) tot += smm[q];
            atomicAdd(&g_mse_sum, (double)tot);
        }
    }
}

// ---------------------------------------------------------------------------
// Per-row softmax(ALPHA*att) + argmax + hard_quantized + fp16 sa.
// sa/hardq live in d_out -> only 8B-aligned: scalar/float2 accesses.
__global__ __launch_bounds__(128) void softmax_kernel(
    const float* __restrict__ att, const float* __restrict__ W,
    float* __restrict__ sa, float* __restrict__ argm_out,
    float* __restrict__ hardq)
{
    int row = blockIdx.x;
    int t = threadIdx.x;
    const float* ar = att + (size_t)row * KC;

    float v[8];
    float m = -3.4e38f;
    int mi = 0;
    #pragma unroll
    for (int j = 0; j < 8; j++) {
        int k = t + j * 128;
        float x = ar[k];
        v[j] = x;
        if (x > m) { m = x; mi = k; }
    }

    __shared__ float smx[128];
    __shared__ int   si[128];
    smx[t] = m; si[t] = mi;
    __syncthreads();
    #pragma unroll
    for (int s = 64; s > 0; s >>= 1) {
        if (t < s) {
            float o = smx[t + s]; int oi = si[t + s];
            if (o > smx[t] || (o == smx[t] && oi < si[t])) { smx[t] = o; si[t] = oi; }
        }
        __syncthreads();
    }
    float rowmax = smx[0];
    int arg = si[0];
    __syncthreads();

    float lsum = 0.0f;
    #pragma unroll
    for (int j = 0; j < 8; j++) {
        v[j] = expf(ALPHA * (v[j] - rowmax));
        lsum += v[j];
    }
    smx[t] = lsum;
    __syncthreads();
    #pragma unroll
    for (int s = 64; s > 0; s >>= 1) {
        if (t < s) smx[t] += smx[t + s];
        __syncthreads();
    }
    float inv = 1.0f / smx[0];

    float* sr = sa + (size_t)row * KC;
    size_t rb = (size_t)row * KC;
    #pragma unroll
    for (int j = 0; j < 8; j++) {
        int k = t + j * 128;
        float p = v[j] * inv;
        sr[k] = p;
        g_sah[rb + k] = __float2half_rn(p);
    }

    if (t == 0) {
        argm_out[row] = (float)arg;
        g_rowmax[row] = rowmax;
    }
    // hard_quantized[row,:] = W[arg,:]  (8B-aligned -> float2)
    const float2* wr = (const float2*)(W + (size_t)arg * DD);
    float2* hq = (float2*)(hardq + (size_t)row * DD);
    hq[2 * t + 0] = wr[2 * t + 0];
    hq[2 * t + 1] = wr[2 * t + 1];
}

// ---------------------------------------------------------------------------
// Column sums of soft_assign (reads fp16 copy). grid (KC/256, BSZ/1024).
__global__ __launch_bounds__(256) void colsum_kernel()
{
    int k = blockIdx.x * 256 + threadIdx.x;
    int r0 = blockIdx.y * 1024;
    float s = 0.0f;
    for (int r = 0; r < 1024; r++)
        s += __half2float(g_sah[(size_t)(r0 + r) * KC + k]);
    atomicAdd(&g_avg[k], s);
}

// ---------------------------------------------------------------------------
// Final scalars: vq_loss (from fused mse), entropy_vq, cluster_metric (rowmax).
__global__ __launch_bounds__(1024) void finalize_kernel(float* __restrict__ out)
{
    int t = threadIdx.x;
    float p = g_avg[t] * (1.0f / (float)BSZ);
    float ent = p * logf(p + 1e-10f);
    float rmx = 0.0f;
    #pragma unroll
    for (int j = 0; j < 16; j++) rmx += g_rowmax[t + j * 1024];
    __shared__ float se[1024];
    __shared__ float sr[1024];
    se[t] = ent; sr[t] = rmx;
    __syncthreads();
    #pragma unroll
    for (int s = 512; s > 0; s >>= 1) {
        if (t < s) { se[t] += se[t + s]; sr[t] += sr[t + s]; }
        __syncthreads();
    }
    if (t == 0) {
        double mse = g_mse_sum / (double)((size_t)BSZ * DD);
        out[OFF_VQ]  = (float)((1.0 + (double)BETA) * mse);
        out[OFF_ENT] = -se[0];
        out[OFF_CM]  = (float)((double)sr[0] / (double)BSZ);
    }
}

// ---------------------------------------------------------------------------
extern "C" void kernel_launch(void* const* d_in, const int* in_sizes, int n_in,
                              void* d_out, int out_size)
{
    const float* latents = (const float*)d_in[0];   // [B, D]
    const float* emb     = (const float*)d_in[1];   // [K, D]
    float* out = (float*)d_out;

    float* ln  = 0; cudaGetSymbolAddress((void**)&ln,  g_ln);
    float* att = 0; cudaGetSymbolAddress((void**)&att, g_att);
    __nv_bfloat16 *lnh=0,*lnl=0,*cbh=0,*cbl=0;
    __half *sah=0,*wth=0;
    cudaGetSymbolAddress((void**)&lnh, g_lnh);
    cudaGetSymbolAddress((void**)&lnl, g_lnl);
    cudaGetSymbolAddress((void**)&cbh, g_cbh);
    cudaGetSymbolAddress((void**)&cbl, g_cbl);
    cudaGetSymbolAddress((void**)&sah, g_sah);
    cudaGetSymbolAddress((void**)&wth, g_wth);

    cudaFuncSetAttribute((const void*)hmma_gemm_kernel<__nv_bfloat16, 4, false>,
                         cudaFuncAttributeMaxDynamicSharedMemorySize, 2 * 4 * TILE_B);
    cudaFuncSetAttribute((const void*)hmma_gemm_kernel<__half, 2, true>,
                         cudaFuncAttributeMaxDynamicSharedMemorySize, 2 * 2 * TILE_B);

    float* q_out   = out + OFF_Q;
    float* arg_out = out + OFF_ARG;
    float* hq_out  = out + OFF_HQ;
    float* sa_out  = out + OFF_SA;

    init_kernel<<<1, 1024>>>();
    l2norm_split_kernel<false><<<KC, 128>>>(emb, 0, cbh, cbl);
    l2norm_split_kernel<true><<<BSZ, 128>>>(latents, ln, lnh, lnl);
    {
        dim3 grid(KC / 32, DD / 32);
        transpose_h_kernel<<<grid, 1024>>>(emb, wth);
    }

    // attention = ln [B,512] * cbn [1024,512]^T  (bf16 x3, fp32 acc)
    {
        dim3 grid(KC / 128, BSZ / 128);
        hmma_gemm_kernel<__nv_bfloat16, 4, false>
            <<<grid, GTHREADS, 2 * 4 * TILE_B>>>(lnh, lnl, cbh, cbl, att, 0, KC, DD);
    }

    softmax_kernel<<<BSZ, 128>>>(att, emb, sa_out, arg_out, hq_out);
    {
        dim3 grid(KC / 256, BSZ / 1024);
        colsum_kernel<<<grid, 256>>>();
    }

    // quantized = sa [B,1024] * Wt [512,1024]^T  (fp16 x1, fp32 acc, fused MSE)
    {
        dim3 grid(DD / 128, BSZ / 128);
        hmma_gemm_kernel<__half, 2, true>
            <<<grid, GTHREADS, 2 * 2 * TILE_B>>>(sah, 0, wth, 0, q_out, ln, DD, KC);
    }

    finalize_kernel<<<1, 1024>>>(out);
}

// round 11
// speedup vs baseline: 3.8246x; 1.4052x over previous
#include <cuda_runtime.h>
#include <cuda_fp16.h>
#include <math.h>
#include <stdint.h>

// Problem constants
#define BSZ 16384
#define DD  512
#define KC  1024
#define ALPHA 10.0f
#define BETA  0.25f
#define TAU  1e-3f          // argmax ambiguity threshold (logit units)

// Output layout (concatenated fp32):
//  quantized [B,D], vq_loss [1], entropy_vq [1], argm [B], hard_quantized [B,D],
//  soft_assign [B,K], cluster_metric [1]
// OFF_HQ / OFF_SA are == 2 mod 4 floats -> only 8-byte aligned.
#define OFF_Q   ((size_t)0)
#define OFF_VQ  ((size_t)(BSZ*DD))
#define OFF_ENT (OFF_VQ + 1)
#define OFF_ARG (OFF_ENT + 1)
#define OFF_HQ  (OFF_ARG + BSZ)
#define OFF_SA  (OFF_HQ + (size_t)BSZ*DD)
#define OFF_CM  (OFF_SA + (size_t)BSZ*KC)

// ---------------------------------------------------------------------------
// Scratch (device globals; no allocation allowed).
__device__ float  g_ln [(size_t)BSZ * DD];   // normalized latents fp32
__device__ float  g_cbn[(size_t)KC * DD];    // normalized codebook fp32 (recheck)
__device__ float  g_att[(size_t)BSZ * KC];   // attention logits (fp16x1 approx)
__device__ __align__(128) __half g_lnh[(size_t)BSZ * DD];   // ln fp16
__device__ __align__(128) __half g_cbh[(size_t)KC * DD];    // cbn fp16
__device__ __align__(128) __half g_sah[(size_t)BSZ * KC];   // sa fp16
__device__ __align__(128) __half g_wth[(size_t)DD * KC];    // W^T fp16 [D,K]
__device__ float  g_rowmax[BSZ];
__device__ float  g_avg[KC];
__device__ double g_mse_sum;

// ---------------------------------------------------------------------------
// Baseline-PTX helpers (valid on compute_103): cp.async, ldmatrix, mma.sync
__device__ __forceinline__ uint32_t smem_u32(const void* p) {
    return (uint32_t)__cvta_generic_to_shared(p);
}
__device__ __forceinline__ void cp_async16(uint32_t saddr, const void* gaddr) {
    asm volatile("cp.async.cg.shared.global [%0], [%1], 16;"
                 :: "r"(saddr), "l"(gaddr) : "memory");
}
__device__ __forceinline__ void cp_commit() {
    asm volatile("cp.async.commit_group;" ::: "memory");
}
__device__ __forceinline__ void cp_wait0() {
    asm volatile("cp.async.wait_group 0;" ::: "memory");
}
__device__ __forceinline__ void cp_wait1() {
    asm volatile("cp.async.wait_group 1;" ::: "memory");
}
__device__ __forceinline__ void ldsm_x4(uint32_t& r0, uint32_t& r1,
                                        uint32_t& r2, uint32_t& r3, uint32_t a) {
    asm volatile("ldmatrix.sync.aligned.m8n8.x4.shared.b16 {%0,%1,%2,%3}, [%4];"
                 : "=r"(r0), "=r"(r1), "=r"(r2), "=r"(r3) : "r"(a));
}
__device__ __forceinline__ void mma_h(float* c, const uint32_t* a, const uint32_t* b) {
    asm volatile(
        "mma.sync.aligned.m16n8k16.row.col.f32.f16.f16.f32 "
        "{%0,%1,%2,%3}, {%4,%5,%6,%7}, {%8,%9}, {%0,%1,%2,%3};"
        : "+f"(c[0]), "+f"(c[1]), "+f"(c[2]), "+f"(c[3])
        : "r"(a[0]), "r"(a[1]), "r"(a[2]), "r"(a[3]), "r"(b[0]), "r"(b[1]));
}

// ---------------------------------------------------------------------------
__global__ void init_kernel() {
    int t = threadIdx.x;
    if (t < KC) g_avg[t] = 0.0f;
    if (t == 0) g_mse_sum = 0.0;
}

// ---------------------------------------------------------------------------
// Row L2 normalize -> fp32 + fp16. One block (128 thr) per row of 512.
__global__ __launch_bounds__(128) void l2norm_kernel(
    const float* __restrict__ x, float* __restrict__ y, __half* __restrict__ yh)
{
    int r = blockIdx.x;
    int t = threadIdx.x;
    const float4* xr = (const float4*)(x + (size_t)r * DD);
    float4 v = xr[t];
    float s = v.x * v.x + v.y * v.y + v.z * v.z + v.w * v.w;
    #pragma unroll
    for (int o = 16; o > 0; o >>= 1) s += __shfl_xor_sync(0xffffffffu, s, o);
    __shared__ float sm[4];
    if ((t & 31) == 0) sm[t >> 5] = s;
    __syncthreads();
    float tot = sm[0] + sm[1] + sm[2] + sm[3];
    float inv = 1.0f / fmaxf(sqrtf(tot), 1e-12f);
    float o0 = v.x * inv, o1 = v.y * inv, o2 = v.z * inv, o3 = v.w * inv;
    ((float4*)(y + (size_t)r * DD))[t] = make_float4(o0, o1, o2, o3);
    __half2 h01 = __floats2half2_rn(o0, o1);
    __half2 h23 = __floats2half2_rn(o2, o3);
    *(__half2*)(yh + (size_t)r * DD + t * 4 + 0) = h01;
    *(__half2*)(yh + (size_t)r * DD + t * 4 + 2) = h23;
}

// ---------------------------------------------------------------------------
// W [KC, DD] -> Wt fp16 [DD, KC]
__global__ __launch_bounds__(1024) void transpose_h_kernel(
    const float* __restrict__ W, __half* __restrict__ th)
{
    __shared__ float tile[32][33];
    int k0 = blockIdx.x * 32, d0 = blockIdx.y * 32;
    int tx = threadIdx.x & 31, ty = threadIdx.x >> 5;
    tile[ty][tx] = W[(size_t)(k0 + ty) * DD + d0 + tx];
    __syncthreads();
    float v = tile[tx][ty];
    th[(size_t)(d0 + ty) * KC + k0 + tx] = __float2half_rn(v);
}

// ---------------------------------------------------------------------------
// HMMA fp16 GEMM, CTA tile 128x128, BK=32, 8 warps (2Mx4N), warp tile 64x32.
// C[M,N] = A[M,Kd] * B[N,Kd]^T  (fp32 accum)
// FUSE: accumulate sum((C - Lref)^2) into g_mse_sum (one atomic per CTA).
// Double-buffered cp.async smem; rows padded to 80B (conflict-free ldmatrix).
#define GTHREADS 256
#define ROWB   80
#define TILE_B (128 * ROWB)          // 10240 bytes per 128x32 fp16 tile
#define STAGE_B (2 * TILE_B)
#define GSMEM (2 * STAGE_B)          // 40960

template<bool FUSE>
__global__ __launch_bounds__(GTHREADS, 1) void hmma_gemm_kernel(
    const __half* __restrict__ A, const __half* __restrict__ B,
    float* __restrict__ C, const float* __restrict__ Lref, int Ntot, int Kd)
{
    extern __shared__ char smraw[];
    int tid = threadIdx.x;
    int w = tid >> 5, l = tid & 31;
    int wm = w & 1, wn = w >> 1;
    int bm = blockIdx.y * 128;
    int bn = blockIdx.x * 128;

    const __half* gtile[2] = { A + (size_t)bm * Kd, B + (size_t)bn * Kd };

    uint32_t sbase = smem_u32(smraw);

    auto load_stage = [&](int kc, int st) {
        uint32_t sb = sbase + st * STAGE_B;
        #pragma unroll
        for (int it = 0; it < 4; it++) {
            int g = it * GTHREADS + tid;
            int tile = g >> 9;
            int c = g & 511;
            int row = c >> 2;
            int col = c & 3;
            const char* src = (const char*)(gtile[tile] + (size_t)row * Kd + kc * 32)
                              + col * 16;
            cp_async16(sb + tile * TILE_B + row * ROWB + col * 16, src);
        }
        cp_commit();
    };

    float acc[4][4][4];
    #pragma unroll
    for (int i = 0; i < 4; i++)
        #pragma unroll
        for (int j = 0; j < 4; j++)
            #pragma unroll
            for (int q = 0; q < 4; q++) acc[i][j][q] = 0.0f;

    int nch = Kd >> 5;
    load_stage(0, 0);

    for (int kc = 0; kc < nch; kc++) {
        int st = kc & 1;
        if (kc + 1 < nch) { load_stage(kc + 1, st ^ 1); cp_wait1(); }
        else              { cp_wait0(); }
        __syncthreads();

        uint32_t ab = sbase + st * STAGE_B;
        uint32_t bb = sbase + st * STAGE_B + TILE_B;

        int ldrow = l & 15;
        int ldcol = (l >> 4) * 16;

        #pragma unroll
        for (int kk = 0; kk < 2; kk++) {
            int kb = kk * 32 + ldcol;
            uint32_t a_r[4][4];
            #pragma unroll
            for (int mt = 0; mt < 4; mt++) {
                uint32_t off = (uint32_t)(wm * 64 + mt * 16 + ldrow) * ROWB + kb;
                ldsm_x4(a_r[mt][0], a_r[mt][1], a_r[mt][2], a_r[mt][3], ab + off);
            }
            uint32_t b_r[4][2];
            #pragma unroll
            for (int np = 0; np < 2; np++) {
                uint32_t off = (uint32_t)(wn * 32 + np * 16 + ldrow) * ROWB + kb;
                uint32_t r0, r1, r2, r3;
                ldsm_x4(r0, r1, r2, r3, bb + off);
                b_r[2 * np][0] = r0; b_r[2 * np][1] = r2;
                b_r[2 * np + 1][0] = r1; b_r[2 * np + 1][1] = r3;
            }
            #pragma unroll
            for (int mt = 0; mt < 4; mt++)
                #pragma unroll
                for (int nt = 0; nt < 4; nt++)
                    mma_h(acc[mt][nt], a_r[mt], b_r[nt]);
        }
        __syncthreads();
    }

    // Epilogue: fp32 float2 stores (+ optional fused (C-Lref)^2 accumulation)
    float msum = 0.0f;
    #pragma unroll
    for (int mt = 0; mt < 4; mt++) {
        int r0 = bm + wm * 64 + mt * 16 + (l >> 2);
        #pragma unroll
        for (int nt = 0; nt < 4; nt++) {
            int cb = bn + wn * 32 + nt * 8 + (l & 3) * 2;
            float2 v01 = make_float2(acc[mt][nt][0], acc[mt][nt][1]);
            float2 v23 = make_float2(acc[mt][nt][2], acc[mt][nt][3]);
            *(float2*)(C + (size_t)r0 * Ntot + cb) = v01;
            *(float2*)(C + (size_t)(r0 + 8) * Ntot + cb) = v23;
            if constexpr (FUSE) {
                float2 l01 = *(const float2*)(Lref + (size_t)r0 * Ntot + cb);
                float2 l23 = *(const float2*)(Lref + (size_t)(r0 + 8) * Ntot + cb);
                float d0 = v01.x - l01.x, d1 = v01.y - l01.y;
                float d2 = v23.x - l23.x, d3 = v23.y - l23.y;
                msum += d0 * d0 + d1 * d1 + d2 * d2 + d3 * d3;
            }
        }
    }
    if constexpr (FUSE) {
        #pragma unroll
        for (int o = 16; o > 0; o >>= 1)
            msum += __shfl_xor_sync(0xffffffffu, msum, o);
        __shared__ float smm[8];
        if (l == 0) smm[w] = msum;
        __syncthreads();
        if (tid == 0) {
            float tot = 0.0f;
            #pragma unroll
            for (int q = 0; q < 8; q++) tot += smm[q];
            atomicAdd(&g_mse_sum, (double)tot);
        }
    }
}

// ---------------------------------------------------------------------------
// Per-row softmax(ALPHA*att) + exact-rechecked argmax + hard_quantized + fp16 sa.
// Logits are fp16x1 approximations (abs err ~2e-5). Softmax / rowmax tolerate
// this; argmax does not, so all candidates within TAU of the row max get an
// exact fp32 dot (ln row from smem x cbn row from L2) and the true max wins.
// sa/hardq live in d_out -> only 8B-aligned: scalar/float2 accesses.
__global__ __launch_bounds__(128) void softmax_kernel(
    const float* __restrict__ att, const float* __restrict__ W,
    const float* __restrict__ ln, const float* __restrict__ cbn,
    float* __restrict__ sa, float* __restrict__ argm_out,
    float* __restrict__ hardq)
{
    int row = blockIdx.x;
    int t = threadIdx.x;
    const float* ar = att + (size_t)row * KC;

    float v[8];
    float m = -3.4e38f;
    int mi = 0;
    #pragma unroll
    for (int j = 0; j < 8; j++) {
        int k = t + j * 128;
        float x = ar[k];
        v[j] = x;
        if (x > m) { m = x; mi = k; }
    }

    __shared__ float smx[128];
    __shared__ int   si[128];
    smx[t] = m; si[t] = mi;
    __syncthreads();
    #pragma unroll
    for (int s = 64; s > 0; s >>= 1) {
        if (t < s) {
            float o = smx[t + s]; int oi = si[t + s];
            if (o > smx[t] || (o == smx[t] && oi < si[t])) { smx[t] = o; si[t] = oi; }
        }
        __syncthreads();
    }
    float rowmax = smx[0];
    int arg = si[0];
    __syncthreads();

    // ---- exact argmax recheck for ambiguous rows ----
    __shared__ int s_cnt;
    __shared__ int s_cand[32];
    __shared__ int s_arg;
    __shared__ float s_red[4];
    __shared__ __align__(16) float s_lnrow[DD];
    if (t == 0) s_cnt = 0;
    __syncthreads();
    #pragma unroll
    for (int j = 0; j < 8; j++) {
        if (v[j] >= rowmax - TAU) {
            int pos = atomicAdd(&s_cnt, 1);
            if (pos < 32) s_cand[pos] = t + j * 128;
        }
    }
    __syncthreads();
    int cnt = s_cnt;
    if (cnt > 1 && cnt <= 32) {
        ((float4*)s_lnrow)[t] = ((const float4*)(ln + (size_t)row * DD))[t];
        __syncthreads();
        float bestv = -3.4e38f;
        int besti = 0x7fffffff;
        for (int c = 0; c < cnt; c++) {
            int k = s_cand[c];
            float4 a = ((const float4*)s_lnrow)[t];
            float4 b = ((const float4*)(cbn + (size_t)k * DD))[t];
            float p = a.x * b.x + a.y * b.y + a.z * b.z + a.w * b.w;
            #pragma unroll
            for (int o = 16; o > 0; o >>= 1) p += __shfl_xor_sync(0xffffffffu, p, o);
            if ((t & 31) == 0) s_red[t >> 5] = p;
            __syncthreads();
            if (t == 0) {
                float d = s_red[0] + s_red[1] + s_red[2] + s_red[3];
                if (d > bestv || (d == bestv && k < besti)) { bestv = d; besti = k; }
            }
            __syncthreads();
        }
        if (t == 0) s_arg = besti;
        __syncthreads();
        arg = s_arg;
    }

    float lsum = 0.0f;
    #pragma unroll
    for (int j = 0; j < 8; j++) {
        v[j] = expf(ALPHA * (v[j] - rowmax));
        lsum += v[j];
    }
    smx[t] = lsum;
    __syncthreads();
    #pragma unroll
    for (int s = 64; s > 0; s >>= 1) {
        if (t < s) smx[t] += smx[t + s];
        __syncthreads();
    }
    float inv = 1.0f / smx[0];

    float* sr = sa + (size_t)row * KC;
    size_t rb = (size_t)row * KC;
    #pragma unroll
    for (int j = 0; j < 8; j++) {
        int k = t + j * 128;
        float p = v[j] * inv;
        sr[k] = p;
        g_sah[rb + k] = __float2half_rn(p);
    }

    if (t == 0) {
        argm_out[row] = (float)arg;
        g_rowmax[row] = rowmax;
    }
    // hard_quantized[row,:] = W[arg,:]  (8B-aligned -> float2)
    const float2* wr = (const float2*)(W + (size_t)arg * DD);
    float2* hq = (float2*)(hardq + (size_t)row * DD);
    hq[2 * t + 0] = wr[2 * t + 0];
    hq[2 * t + 1] = wr[2 * t + 1];
}

// ---------------------------------------------------------------------------
// Column sums of soft_assign (reads fp16 copy). grid (KC/256, BSZ/1024).
__global__ __launch_bounds__(256) void colsum_kernel()
{
    int k = blockIdx.x * 256 + threadIdx.x;
    int r0 = blockIdx.y * 1024;
    float s = 0.0f;
    for (int r = 0; r < 1024; r++)
        s += __half2float(g_sah[(size_t)(r0 + r) * KC + k]);
    atomicAdd(&g_avg[k], s);
}

// ---------------------------------------------------------------------------
// Final scalars: vq_loss (from fused mse), entropy_vq, cluster_metric (rowmax).
__global__ __launch_bounds__(1024) void finalize_kernel(float* __restrict__ out)
{
    int t = threadIdx.x;
    float p = g_avg[t] * (1.0f / (float)BSZ);
    float ent = p * logf(p + 1e-10f);
    float rmx = 0.0f;
    #pragma unroll
    for (int j = 0; j < 16; j++) rmx += g_rowmax[t + j * 1024];
    __shared__ float se[1024];
    __shared__ float sr[1024];
    se[t] = ent; sr[t] = rmx;
    __syncthreads();
    #pragma unroll
    for (int s = 512; s > 0; s >>= 1) {
        if (t < s) { se[t] += se[t + s]; sr[t] += sr[t + s]; }
        __syncthreads();
    }
    if (t == 0) {
        double mse = g_mse_sum / (double)((size_t)BSZ * DD);
        out[OFF_VQ]  = (float)((1.0 + (double)BETA) * mse);
        out[OFF_ENT] = -se[0];
        out[OFF_CM]  = (float)((double)sr[0] / (double)BSZ);
    }
}

// ---------------------------------------------------------------------------
extern "C" void kernel_launch(void* const* d_in, const int* in_sizes, int n_in,
                              void* d_out, int out_size)
{
    const float* latents = (const float*)d_in[0];   // [B, D]
    const float* emb     = (const float*)d_in[1];   // [K, D]
    float* out = (float*)d_out;

    float* ln  = 0; cudaGetSymbolAddress((void**)&ln,  g_ln);
    float* cbn = 0; cudaGetSymbolAddress((void**)&cbn, g_cbn);
    float* att = 0; cudaGetSymbolAddress((void**)&att, g_att);
    __half *lnh = 0, *cbh = 0, *sah = 0, *wth = 0;
    cudaGetSymbolAddress((void**)&lnh, g_lnh);
    cudaGetSymbolAddress((void**)&cbh, g_cbh);
    cudaGetSymbolAddress((void**)&sah, g_sah);
    cudaGetSymbolAddress((void**)&wth, g_wth);

    cudaFuncSetAttribute((const void*)hmma_gemm_kernel<false>,
                         cudaFuncAttributeMaxDynamicSharedMemorySize, GSMEM);
    cudaFuncSetAttribute((const void*)hmma_gemm_kernel<true>,
                         cudaFuncAttributeMaxDynamicSharedMemorySize, GSMEM);

    float* q_out   = out + OFF_Q;
    float* arg_out = out + OFF_ARG;
    float* hq_out  = out + OFF_HQ;
    float* sa_out  = out + OFF_SA;

    init_kernel<<<1, 1024>>>();
    l2norm_kernel<<<KC, 128>>>(emb, cbn, cbh);
    l2norm_kernel<<<BSZ, 128>>>(latents, ln, lnh);
    {
        dim3 grid(KC / 32, DD / 32);
        transpose_h_kernel<<<grid, 1024>>>(emb, wth);
    }

    // attention = ln [B,512] * cbn [1024,512]^T  (fp16 x1, fp32 acc)
    {
        dim3 grid(KC / 128, BSZ / 128);
        hmma_gemm_kernel<false><<<grid, GTHREADS, GSMEM>>>(lnh, cbh, att, 0, KC, DD);
    }

    softmax_kernel<<<BSZ, 128>>>(att, emb, ln, cbn, sa_out, arg_out, hq_out);
    {
        dim3 grid(KC / 256, BSZ / 1024);
        colsum_kernel<<<grid, 256>>>();
    }

    // quantized = sa [B,1024] * Wt [512,1024]^T  (fp16 x1, fp32 acc, fused MSE)
    {
        dim3 grid(DD / 128, BSZ / 128);
        hmma_gemm_kernel<true><<<grid, GTHREADS, GSMEM>>>(sah, wth, q_out, ln, DD, KC);
    }

    finalize_kernel<<<1, 1024>>>(out);
}